// round 1
// baseline (speedup 1.0000x reference)
#include <cuda_runtime.h>
#include <math.h>

// One CTA (256 threads) per row of 1024 floats.
// Each thread owns 4 consecutive elements (float4). Stable compaction of
// finite values to the front via warp-shuffle scan + cross-warp scan in smem,
// scatter into a 4KB shared buffer, then vectorized affine epilogue:
// out[j] = (j < finite_count) ? s[j]*w[j] + b[j] : 0.

#define SIZE 1024
#define THREADS 256

__global__ __launch_bounds__(THREADS)
void nan_dense_kernel(const float* __restrict__ X,
                      const float* __restrict__ w,
                      const float* __restrict__ b,
                      float* __restrict__ out)
{
    __shared__ float s[SIZE];
    __shared__ int warp_off[8];   // exclusive prefix of warp totals
    __shared__ int s_total;

    const int row = blockIdx.x;
    const int t    = threadIdx.x;
    const int lane = t & 31;
    const int wid  = t >> 5;

    const float4 xv = reinterpret_cast<const float4*>(X + (size_t)row * SIZE)[t];

    float v[4] = {xv.x, xv.y, xv.z, xv.w};
    bool fin[4];
    int cnt = 0;
#pragma unroll
    for (int k = 0; k < 4; ++k) {
        fin[k] = isfinite(v[k]);
        cnt += fin[k] ? 1 : 0;
    }

    // Warp-level inclusive scan of per-thread counts.
    int incl = cnt;
#pragma unroll
    for (int d = 1; d < 32; d <<= 1) {
        int n = __shfl_up_sync(0xffffffffu, incl, d);
        if (lane >= d) incl += n;
    }
    if (lane == 31) warp_off[wid] = incl;   // warp total for now
    __syncthreads();

    // Warp 0, lanes 0..7: scan the 8 warp totals -> exclusive offsets + total.
    if (wid == 0 && lane < 8) {
        int ws = warp_off[lane];
        int sc = ws;
#pragma unroll
        for (int d = 1; d < 8; d <<= 1) {
            int n = __shfl_up_sync(0xffu, sc, d);
            if (lane >= d) sc += n;
        }
        warp_off[lane] = sc - ws;           // exclusive
        if (lane == 7) s_total = sc;        // block total
    }
    __syncthreads();

    // Scatter finite values, stable order.
    int pos = warp_off[wid] + (incl - cnt);
#pragma unroll
    for (int k = 0; k < 4; ++k) {
        if (fin[k]) s[pos++] = v[k];
    }
    __syncthreads();

    const int total = s_total;
    const float4 wv = reinterpret_cast<const float4*>(w)[t];
    const float4 bv = reinterpret_cast<const float4*>(b)[t];
    const float4 sv = reinterpret_cast<const float4*>(s)[t];

    const int base = t << 2;
    float4 o;
    o.x = (base + 0 < total) ? fmaf(sv.x, wv.x, bv.x) : 0.0f;
    o.y = (base + 1 < total) ? fmaf(sv.y, wv.y, bv.y) : 0.0f;
    o.z = (base + 2 < total) ? fmaf(sv.z, wv.z, bv.z) : 0.0f;
    o.w = (base + 3 < total) ? fmaf(sv.w, wv.w, bv.w) : 0.0f;

    reinterpret_cast<float4*>(out + (size_t)row * SIZE)[t] = o;
}

extern "C" void kernel_launch(void* const* d_in, const int* in_sizes, int n_in,
                              void* d_out, int out_size)
{
    const float* X = (const float*)d_in[0];
    const float* w = (const float*)d_in[1];
    const float* b = (const float*)d_in[2];
    float* out = (float*)d_out;

    const int batch = in_sizes[0] / SIZE;   // 131072
    nan_dense_kernel<<<batch, THREADS>>>(X, w, b, out);
}